// round 1
// baseline (speedup 1.0000x reference)
#include <cuda_runtime.h>

#define NB   256
#define NT   1024
#define NS   7
#define NH   64
#define NL   4
#define NOUT 3

// Thread layout: 256 threads/block, one block per batch element.
//   h = tid & 63  : output-neuron index this thread accumulates for
//   k = tid >> 6  : K-slice (each thread owns 16 of the 64 input weights)
// Membranes for all 4 layers are replicated across the 4 k-slices, so the
// hidden-state write is one coalesced STG.32 per thread per step.
__global__ __launch_bounds__(256, 2)
void snn_kernel(const float* __restrict__ x,
                const float* __restrict__ hidden0,
                const float* __restrict__ w1,
                const float* __restrict__ b1,
                const float* __restrict__ w_h,
                const float* __restrict__ b_h,
                const float* __restrict__ w_out,
                const float* __restrict__ b_out,
                float* __restrict__ out_outputs,   // (B,T,OUT)
                float* __restrict__ out_hidden)    // (B,T,L,H)
{
    const int b   = blockIdx.x;
    const int tid = threadIdx.x;
    const int h   = tid & 63;
    const int k   = tid >> 6;

    __shared__ float s_sh[NH];       // spikes of current layer (float 0/1)
    __shared__ float part[4 * NH];   // K-slice partial sums

    // ---- load weights into registers ----
    float wh_reg[3][16];
#pragma unroll
    for (int l = 0; l < 3; ++l)
#pragma unroll
        for (int j = 0; j < 16; ++j)
            wh_reg[l][j] = w_h[(l * NH + h) * NH + k * 16 + j];

    float w1_reg[NS];
#pragma unroll
    for (int s = 0; s < NS; ++s) w1_reg[s] = w1[h * NS + s];
    const float b1_reg = b1[h];

    float bh_reg[3];
#pragma unroll
    for (int l = 0; l < 3; ++l) bh_reg[l] = b_h[l * NH + h];

    float wout_reg[16];
    float bout_reg = 0.0f;
    if (h < NOUT) {
#pragma unroll
        for (int j = 0; j < 16; ++j) wout_reg[j] = w_out[h * NH + k * 16 + j];
        bout_reg = b_out[h];
    }

    // ---- initial membrane state: hidden_states[b, 0, l, h] ----
    float mem[NL];
#pragma unroll
    for (int l = 0; l < NL; ++l)
        mem[l] = hidden0[(size_t)b * NT * NL * NH + l * NH + h];

    // ---- x prefetch (one step ahead) ----
    const float* xb = x + (size_t)b * NT * NS;
    float xr[NS];
#pragma unroll
    for (int s = 0; s < NS; ++s) xr[s] = __ldg(&xb[s]);

    float* hs_out = out_hidden + (size_t)b * NT * NL * NH + k * NH + h;
    float* o_out  = out_outputs + (size_t)b * NT * NOUT + h;

    for (int t = 0; t < NT; ++t) {
        // input current: cur0[h] = sum_s x[b,t,s] * w1[h,s] + b1[h]
        float cur = b1_reg;
#pragma unroll
        for (int s = 0; s < NS; ++s) cur = fmaf(xr[s], w1_reg[s], cur);

        // prefetch next step's x while we compute
        if (t + 1 < NT) {
#pragma unroll
            for (int s = 0; s < NS; ++s) xr[s] = __ldg(&xb[(t + 1) * NS + s]);
        }

        // ---- hidden layers 0..2 ----
#pragma unroll
        for (int l = 0; l < 3; ++l) {
            float m     = mem[l];
            float reset = (m > 1.0f) ? 1.0f : 0.0f;
            // match reference association: ((BETA*m) + cur) - reset  (no FMA fusion)
            float mn    = __fsub_rn(__fadd_rn(__fmul_rn(0.8f, m), cur), reset);
            mem[l] = mn;
            float spk = ((mn - 1.0f) > 0.0f) ? 1.0f : 0.0f;
            if (k == 0) s_sh[h] = spk;
            __syncthreads();

            float p = 0.0f;
#pragma unroll
            for (int j = 0; j < 16; ++j)
                p = fmaf(s_sh[k * 16 + j], wh_reg[l][j], p);
            part[k * 64 + h] = p;
            __syncthreads();

            cur = __fadd_rn(
                    __fadd_rn(__fadd_rn(part[h], part[64 + h]),
                              __fadd_rn(part[128 + h], part[192 + h])),
                    bh_reg[l]);
        }

        // ---- output layer (l = 3) ----
        {
            float m     = mem[3];
            float reset = (m > 1.0f) ? 1.0f : 0.0f;
            float mn    = __fsub_rn(__fadd_rn(__fmul_rn(0.8f, m), cur), reset);
            mem[3] = mn;
            float spk = ((mn - 1.0f) > 0.0f) ? 1.0f : 0.0f;
            if (k == 0) s_sh[h] = spk;
            __syncthreads();

            if (h < NOUT) {
                float p = 0.0f;
#pragma unroll
                for (int j = 0; j < 16; ++j)
                    p = fmaf(s_sh[k * 16 + j], wout_reg[j], p);
                part[k * 64 + h] = p;
            }
            __syncthreads();

            if ((k == 0) && (h < NOUT)) {
                float o = __fadd_rn(
                            __fadd_rn(__fadd_rn(part[h], part[64 + h]),
                                      __fadd_rn(part[128 + h], part[192 + h])),
                            bout_reg);
                o_out[(size_t)t * NOUT] = o;
            }
        }

        // hidden-state write: thread (k,h) writes layer k (fully coalesced)
        hs_out[(size_t)t * NL * NH] = mem[k];
    }
}

// x passthrough: third tuple element of the reference output
__global__ void copy_kernel(const float4* __restrict__ src,
                            float4* __restrict__ dst, int n4)
{
    int i = blockIdx.x * blockDim.x + threadIdx.x;
    if (i < n4) dst[i] = src[i];
}

extern "C" void kernel_launch(void* const* d_in, const int* in_sizes, int n_in,
                              void* d_out, int out_size)
{
    const float* x      = (const float*)d_in[0];
    const float* hidden = (const float*)d_in[1];
    // d_in[2] = prev_obs (unused by reference)
    const float* w1     = (const float*)d_in[3];
    const float* b1     = (const float*)d_in[4];
    const float* w_h    = (const float*)d_in[5];
    const float* b_h    = (const float*)d_in[6];
    const float* w_out  = (const float*)d_in[7];
    const float* b_out  = (const float*)d_in[8];

    float* out         = (float*)d_out;
    float* out_outputs = out;                                   // B*T*OUT
    float* out_hidden  = out_outputs + (size_t)NB * NT * NOUT;  // B*T*L*H
    float* out_x       = out_hidden + (size_t)NB * NT * NL * NH;// B*T*S

    snn_kernel<<<NB, 256>>>(x, hidden, w1, b1, w_h, b_h, w_out, b_out,
                            out_outputs, out_hidden);

    const int n4 = (NB * NT * NS) / 4;  // 1,835,008 floats -> 458,752 float4
    copy_kernel<<<(n4 + 255) / 256, 256>>>((const float4*)x, (float4*)out_x, n4);
}